// round 2
// baseline (speedup 1.0000x reference)
#include <cuda_runtime.h>
#include <math.h>

#define BB 16
#define TT 28
#define NN 2048
#define HH 32
#define LL 8

typedef unsigned long long u64;

// -------- scratch (device globals; no allocation allowed) --------
__device__ float g_Qt[BB*HH*NN];   // Q transposed [b][h][n], pre-scaled by (1-geo)/sqrt(H)*log2e
__device__ float g_Kt[BB*HH*NN];   // K transposed [b][h][n]
__device__ float g_V [BB*NN*HH];   // V natural    [b][n][h]
__device__ float g_ds[BB*NN];      // delayed signal [b][n]

// -------- packed f32x2 helpers (Blackwell) --------
__device__ __forceinline__ u64 dup2(float x) {
    u64 r; asm("mov.b64 %0,{%1,%1};" : "=l"(r) : "f"(x)); return r;
}
__device__ __forceinline__ void fma2(u64 &d, u64 a, u64 b) {
    asm("fma.rn.f32x2 %0,%1,%2,%0;" : "+l"(d) : "l"(a), "l"(b));
}
__device__ __forceinline__ u64 mul2(u64 a, u64 b) {
    u64 d; asm("mul.rn.f32x2 %0,%1,%2;" : "=l"(d) : "l"(a), "l"(b)); return d;
}
__device__ __forceinline__ void unpk2(u64 a, float &lo, float &hi) {
    asm("mov.b64 {%0,%1},%2;" : "=f"(lo), "=f"(hi) : "l"(a));
}

// =====================================================================
// Kernel 1: delayed signal
// =====================================================================
__global__ void ds_kernel(const float* __restrict__ x, const float* __restrict__ logits)
{
    int b = blockIdx.y;
    int n = blockIdx.x * 256 + threadIdx.x;
    float lw[LL];
    float m = -1e30f;
#pragma unroll
    for (int t = 0; t < LL; t++) { lw[t] = logits[t]; m = fmaxf(m, lw[t]); }
    float s = 0.f, e[LL];
#pragma unroll
    for (int t = 0; t < LL; t++) { e[t] = expf(lw[t] - m); s += e[t]; }
    float inv = 1.f / s;
    float acc = 0.f;
#pragma unroll
    for (int tau = 0; tau < LL; tau++) {
        acc += e[tau] * inv * x[((size_t)b * TT + (TT - 1 - tau)) * NN + n];
    }
    g_ds[b * NN + n] = acc;
}

// =====================================================================
// Kernel 2: QKV projections (Q pre-scaled by (1-geo)/sqrt(H)*log2e)
// =====================================================================
__global__ void qkv_kernel(const float* __restrict__ features,
                           const float* __restrict__ Wq, const float* __restrict__ bq,
                           const float* __restrict__ Wk, const float* __restrict__ bk,
                           const float* __restrict__ Wv, const float* __restrict__ bv,
                           const float* __restrict__ gw)
{
    __shared__ float Ws[3][32 * 32];
    __shared__ float bs[3][32];
    __shared__ float vsm[256 * 33];

    int b = blockIdx.y;
    int n0 = blockIdx.x * 256;
    int tid = threadIdx.x;

    for (int i = tid; i < 1024; i += 256) {
        Ws[0][i] = Wq[i]; Ws[1][i] = Wk[i]; Ws[2][i] = Wv[i];
    }
    if (tid < 32) { bs[0][tid] = bq[tid]; bs[1][tid] = bk[tid]; bs[2][tid] = bv[tid]; }
    __syncthreads();

    float geo = 1.f / (1.f + expf(-gw[0]));
    float csq = (1.f - geo) * 0.17677669529663687f * 1.4426950408889634f;

    int n = n0 + tid;
    float4 rf[8];
    const float* fp = features + ((size_t)b * NN + n) * HH;
#pragma unroll
    for (int i = 0; i < 8; i++) rf[i] = *(const float4*)(fp + i * 4);

#pragma unroll 4
    for (int j = 0; j < 32; j++) {
        float aq = bs[0][j], ak = bs[1][j], av = bs[2][j];
#pragma unroll
        for (int i = 0; i < 8; i++) {
            float4 wq4 = *(float4*)&Ws[0][j * 32 + i * 4];
            float4 wk4 = *(float4*)&Ws[1][j * 32 + i * 4];
            float4 wv4 = *(float4*)&Ws[2][j * 32 + i * 4];
            aq += rf[i].x * wq4.x + rf[i].y * wq4.y + rf[i].z * wq4.z + rf[i].w * wq4.w;
            ak += rf[i].x * wk4.x + rf[i].y * wk4.y + rf[i].z * wk4.z + rf[i].w * wk4.w;
            av += rf[i].x * wv4.x + rf[i].y * wv4.y + rf[i].z * wv4.z + rf[i].w * wv4.w;
        }
        g_Qt[((size_t)b * HH + j) * NN + n] = csq * aq;
        g_Kt[((size_t)b * HH + j) * NN + n] = ak;
        vsm[tid * 33 + j] = av;
    }
    __syncthreads();
    for (int ch = 0; ch < 32; ch++) {
        int idx = ch * 256 + tid;
        int r = idx >> 5, h = idx & 31;
        g_V[((size_t)b * NN + n0 + r) * HH + h] = vsm[r * 33 + h];
    }
}

// =====================================================================
// Kernel 3: flash attention + propagation + out-proj + LayerNorm.
//   128 q-rows x 1 batch per CTA, 256 threads, 128-wide key tiles.
//   S phase:  16x16 thread grid, 8x8 outputs/thread, packed f32x2 FMA.
//   PV phase: (rowg16 x hg4 x cs4), 8 rows x 8 h per thread over 32 c's;
//             c-split partials reduced in the epilogue.
// =====================================================================
#define SMF 30336
#define SMEM_BYTES (SMF * 4)

__global__ void __launch_bounds__(256, 1) attn_kernel(
    const float* __restrict__ adj, const float* __restrict__ features,
    const float* __restrict__ gw,  const float* __restrict__ Wo,
    const float* __restrict__ bo,  const float* __restrict__ gamma,
    const float* __restrict__ beta, float* __restrict__ out)
{
    extern __shared__ float sm[];
    float* Qs   = sm;            // [32][128]  4096
    float* Ks   = sm + 4096;     // [32][128]  4096
    float* Vs   = sm + 8192;     // [128][36]  4608
    float* Ps   = sm + 12800;    // [128][132] 16896  (alias: part[4][128][33])
    float* dss  = sm + 29696;    // [128]
    float* m_s  = sm + 29824;    // [128]
    float* l_s  = sm + 29952;    // [128]
    float* pr_s = sm + 30080;    // [128]
    float* al_s = sm + 30208;    // [128]
    // epilogue aliases
    float* Cs   = sm;            // [128][33] over Qs/Ks (dead)
    float* Wos  = sm + 8192;     // [32][33]  over Vs (dead)
    float* bos  = Wos + 32 * 33;
    float* gms  = bos + 32;
    float* bts  = gms + 32;
    float* part = Ps;            // [4][128][33]

    const int b   = blockIdx.y;
    const int n0  = blockIdx.x * 128;
    const int tid = threadIdx.x;
    const int ty  = tid >> 4;          // 0..15 (row group: rows ty*8..+7; same for S and PV)
    const int tx  = tid & 15;          // 0..15 (S col group: cols tx*8..+7)
    const int hg  = (tid >> 2) & 3;    // PV: h group (8 h)
    const int cs  = tid & 3;           // PV: c split (32 c)
    const int r0  = ty * 8;

    const float LOG2E = 1.4426950408889634f;
    float geo = 1.f / (1.f + expf(-gw[0]));
    u64 cg2 = dup2(geo * 5.f * LOG2E);

    // resident Q tile [k][row]
    for (int i = tid; i < 1024; i += 256) {
        int k = i >> 5, c = (i & 31) << 2;
        *(float4*)&Qs[k * 128 + c] = *(const float4*)&g_Qt[((size_t)b * HH + k) * NN + n0 + c];
    }
    if (tid < 128) { m_s[tid] = -INFINITY; l_s[tid] = 0.f; pr_s[tid] = 0.f; }

    u64 acc2[8][4];
#pragma unroll
    for (int i = 0; i < 8; i++)
#pragma unroll
        for (int j = 0; j < 4; j++) acc2[i][j] = 0ull;

    for (int m0 = 0; m0 < NN; m0 += 128) {
        __syncthreads();   // prev PV done (Vs/Ps free); init visible on iter 0

        // adj -> accumulator init (gmem latency overlaps smem fills below)
        u64 sp[8][4];
#pragma unroll
        for (int i = 0; i < 8; i++) {
            const float* ar = adj + (size_t)(n0 + r0 + i) * NN + m0 + tx * 8;
            ulonglong2 a01 = *(const ulonglong2*)ar;
            ulonglong2 a23 = *(const ulonglong2*)(ar + 4);
            sp[i][0] = mul2(cg2, a01.x); sp[i][1] = mul2(cg2, a01.y);
            sp[i][2] = mul2(cg2, a23.x); sp[i][3] = mul2(cg2, a23.y);
        }
        // K tile [k][c], V tile [c][h], ds
        for (int i = tid; i < 1024; i += 256) {
            int k = i >> 5, c = (i & 31) << 2;
            *(float4*)&Ks[k * 128 + c] = *(const float4*)&g_Kt[((size_t)b * HH + k) * NN + m0 + c];
        }
        for (int i = tid; i < 1024; i += 256) {
            int c = i >> 3, h = (i & 7) << 2;
            *(float4*)&Vs[c * 36 + h] = *(const float4*)&g_V[((size_t)b * NN + m0 + c) * HH + h];
        }
        if (tid < 128) dss[tid] = g_ds[b * NN + m0 + tid];
        __syncthreads();

        // ---- S = Q^T K + cg*adj  (8 rows x 8 cols per thread, f32x2) ----
#pragma unroll 4
        for (int k = 0; k < 32; k++) {
            float4 qa = *(float4*)&Qs[k * 128 + r0];
            float4 qb = *(float4*)&Qs[k * 128 + r0 + 4];
            ulonglong2 k01 = *(ulonglong2*)&Ks[k * 128 + tx * 8];
            ulonglong2 k23 = *(ulonglong2*)&Ks[k * 128 + tx * 8 + 4];
            float qv[8] = {qa.x, qa.y, qa.z, qa.w, qb.x, qb.y, qb.z, qb.w};
#pragma unroll
            for (int i = 0; i < 8; i++) {
                u64 qd = dup2(qv[i]);
                fma2(sp[i][0], qd, k01.x); fma2(sp[i][1], qd, k01.y);
                fma2(sp[i][2], qd, k23.x); fma2(sp[i][3], qd, k23.y);
            }
        }

        // ---- online softmax (rows spread over 16 lanes, width-16 shfl) ----
        float dsr[8];
        *(float4*)&dsr[0] = *(float4*)&dss[tx * 8];
        *(float4*)&dsr[4] = *(float4*)&dss[tx * 8 + 4];
#pragma unroll
        for (int i = 0; i < 8; i++) {
            float sv[8];
#pragma unroll
            for (int jp = 0; jp < 4; jp++) unpk2(sp[i][jp], sv[2 * jp], sv[2 * jp + 1]);
            float rm = sv[0];
#pragma unroll
            for (int j = 1; j < 8; j++) rm = fmaxf(rm, sv[j]);
#pragma unroll
            for (int off = 1; off < 16; off <<= 1)
                rm = fmaxf(rm, __shfl_xor_sync(0xffffffffu, rm, off, 16));
            int r = r0 + i;
            float mo = m_s[r];
            float mn = fmaxf(mo, rm);
            float al = exp2f(mo - mn);
            float sum = 0.f, pr = 0.f;
#pragma unroll
            for (int j = 0; j < 8; j++) {
                float p = exp2f(sv[j] - mn); sv[j] = p; sum += p; pr += p * dsr[j];
            }
#pragma unroll
            for (int off = 1; off < 16; off <<= 1) {
                sum += __shfl_xor_sync(0xffffffffu, sum, off, 16);
                pr  += __shfl_xor_sync(0xffffffffu, pr,  off, 16);
            }
            *(float4*)&Ps[r * 132 + tx * 8]     = make_float4(sv[0], sv[1], sv[2], sv[3]);
            *(float4*)&Ps[r * 132 + tx * 8 + 4] = make_float4(sv[4], sv[5], sv[6], sv[7]);
            if (tx == 0) {
                m_s[r]  = mn;
                al_s[r] = al;
                l_s[r]  = l_s[r]  * al + sum;
                pr_s[r] = pr_s[r] * al + pr;
            }
        }
        __syncthreads();

        // ---- PV: acc += P*V over this thread's 32-c slice (f32x2) ----
#pragma unroll
        for (int i = 0; i < 8; i++) {
            u64 a2 = dup2(al_s[r0 + i]);
#pragma unroll
            for (int jp = 0; jp < 4; jp++) acc2[i][jp] = mul2(acc2[i][jp], a2);
        }
        const int cbase = cs * 32;
#pragma unroll 4
        for (int cc = 0; cc < 32; cc++) {
            int c = cbase + cc;
            ulonglong2 v01 = *(ulonglong2*)&Vs[c * 36 + hg * 8];
            ulonglong2 v23 = *(ulonglong2*)&Vs[c * 36 + hg * 8 + 4];
#pragma unroll
            for (int i = 0; i < 8; i++) {
                u64 pd = dup2(Ps[(r0 + i) * 132 + c]);
                fma2(acc2[i][0], pd, v01.x); fma2(acc2[i][1], pd, v01.y);
                fma2(acc2[i][2], pd, v23.x); fma2(acc2[i][3], pd, v23.y);
            }
        }
    }
    __syncthreads();

    // ---- stage c-split partials: part[cs][r][h] (aliases Ps) ----
#pragma unroll
    for (int i = 0; i < 8; i++) {
        float* pp = &part[((size_t)cs * 128 + (r0 + i)) * 33 + hg * 8];
#pragma unroll
        for (int jp = 0; jp < 4; jp++) {
            float lo, hi; unpk2(acc2[i][jp], lo, hi);
            pp[2 * jp] = lo; pp[2 * jp + 1] = hi;
        }
    }
    for (int i = tid; i < 1024; i += 256) Wos[(i >> 5) * 33 + (i & 31)] = Wo[i];
    if (tid < 32) { bos[tid] = bo[tid]; gms[tid] = gamma[tid]; bts[tid] = beta[tid]; }
    __syncthreads();

    // ---- combined = features + attended/l + 0.1*prop/l ----
    {
        int r = tid >> 1, h0 = (tid & 1) * 16;
        float invl = 1.f / l_s[r];
        float pv   = pr_s[r] * invl * 0.1f;
        const float* fp = &features[((size_t)b * NN + n0 + r) * HH + h0];
#pragma unroll
        for (int h4 = 0; h4 < 16; h4 += 4) {
            float4 f4 = *(const float4*)(fp + h4);
            float fe[4] = {f4.x, f4.y, f4.z, f4.w};
#pragma unroll
            for (int e = 0; e < 4; e++) {
                int h = h0 + h4 + e;
                float s = part[(0 * 128 + r) * 33 + h] + part[(1 * 128 + r) * 33 + h]
                        + part[(2 * 128 + r) * 33 + h] + part[(3 * 128 + r) * 33 + h];
                Cs[r * 33 + h] = fe[e] + s * invl + pv;
            }
        }
    }
    __syncthreads();

    // ---- out-proj + LayerNorm (one row per thread) ----
    if (tid < 128) {
        float cr[32], ho[32];
#pragma unroll
        for (int h = 0; h < 32; h++) cr[h] = Cs[tid * 33 + h];
        float mu = 0.f;
#pragma unroll
        for (int j = 0; j < 32; j++) {
            float a = bos[j];
#pragma unroll
            for (int h = 0; h < 32; h++) a += cr[h] * Wos[j * 33 + h];
            ho[j] = a; mu += a;
        }
        mu *= 0.03125f;
        float var = 0.f;
#pragma unroll
        for (int j = 0; j < 32; j++) { float d = ho[j] - mu; var += d * d; }
        var *= 0.03125f;
        float rs = rsqrtf(var + 1e-5f);
        float* op = out + ((size_t)b * NN + n0 + tid) * HH;
#pragma unroll
        for (int j4 = 0; j4 < 32; j4 += 4) {
            float4 o4;
            o4.x = (ho[j4 + 0] - mu) * rs * gms[j4 + 0] + bts[j4 + 0];
            o4.y = (ho[j4 + 1] - mu) * rs * gms[j4 + 1] + bts[j4 + 1];
            o4.z = (ho[j4 + 2] - mu) * rs * gms[j4 + 2] + bts[j4 + 2];
            o4.w = (ho[j4 + 3] - mu) * rs * gms[j4 + 3] + bts[j4 + 3];
            *(float4*)(op + j4) = o4;
        }
    }
}

// =====================================================================
extern "C" void kernel_launch(void* const* d_in, const int* in_sizes, int n_in,
                              void* d_out, int out_size)
{
    const float* x        = (const float*)d_in[0];
    const float* features = (const float*)d_in[1];
    const float* dlog     = (const float*)d_in[2];
    const float* Wq       = (const float*)d_in[3];
    const float* bq       = (const float*)d_in[4];
    const float* Wk       = (const float*)d_in[5];
    const float* bk       = (const float*)d_in[6];
    const float* Wv       = (const float*)d_in[7];
    const float* bv       = (const float*)d_in[8];
    const float* adj      = (const float*)d_in[9];
    const float* gw       = (const float*)d_in[10];
    const float* Wo       = (const float*)d_in[11];
    const float* bo       = (const float*)d_in[12];
    const float* gamma    = (const float*)d_in[13];
    const float* beta     = (const float*)d_in[14];
    float* out = (float*)d_out;

    cudaFuncSetAttribute(attn_kernel, cudaFuncAttributeMaxDynamicSharedMemorySize, SMEM_BYTES);

    ds_kernel<<<dim3(NN / 256, BB), 256>>>(x, dlog);
    qkv_kernel<<<dim3(NN / 256, BB), 256>>>(features, Wq, bq, Wk, bk, Wv, bv, gw);
    attn_kernel<<<dim3(NN / 128, BB), 256, SMEM_BYTES>>>(adj, features, gw, Wo, bo, gamma, beta, out);
}

// round 4
// speedup vs baseline: 4.5880x; 4.5880x over previous
#include <cuda_runtime.h>
#include <math.h>
#include <stdint.h>

#define BB 16
#define TT 28
#define NN 2048
#define HH 32
#define LL 8

// -------- scratch (device globals) --------
__device__ float g_Q[BB*NN*HH];   // tf32-rounded, pre-scaled by (1-geo)/sqrt(H)*log2e, [b][n][h]
__device__ float g_K[BB*NN*HH];   // tf32-rounded [b][n][h]
__device__ float g_V[BB*NN*HH];   // tf32-rounded [b][n][h]
__device__ float g_ds[BB*NN];     // delayed signal [b][n]

__device__ __forceinline__ float tf32r(float f){
    uint32_t u; asm("cvt.rna.tf32.f32 %0,%1;" : "=r"(u) : "f"(f));
    return __uint_as_float(u);
}
__device__ __forceinline__ float ex2(float x){
    float y; asm("ex2.approx.f32 %0,%1;" : "=f"(y) : "f"(x)); return y;
}
__device__ __forceinline__ void mma_tf32(float d[4], const uint32_t a[4], uint32_t b0, uint32_t b1){
    asm("mma.sync.aligned.m16n8k8.row.col.f32.tf32.tf32.f32 "
        "{%0,%1,%2,%3},{%4,%5,%6,%7},{%8,%9},{%0,%1,%2,%3};"
        : "+f"(d[0]),"+f"(d[1]),"+f"(d[2]),"+f"(d[3])
        : "r"(a[0]),"r"(a[1]),"r"(a[2]),"r"(a[3]),"r"(b0),"r"(b1));
}

// =====================================================================
// Kernel 1: delayed signal
// =====================================================================
__global__ void ds_kernel(const float* __restrict__ x, const float* __restrict__ logits)
{
    int b = blockIdx.y;
    int n = blockIdx.x * 256 + threadIdx.x;
    float lw[LL];
    float m = -1e30f;
#pragma unroll
    for (int t = 0; t < LL; t++) { lw[t] = logits[t]; m = fmaxf(m, lw[t]); }
    float s = 0.f, e[LL];
#pragma unroll
    for (int t = 0; t < LL; t++) { e[t] = expf(lw[t] - m); s += e[t]; }
    float inv = 1.f / s;
    float acc = 0.f;
#pragma unroll
    for (int tau = 0; tau < LL; tau++)
        acc += e[tau] * inv * x[((size_t)b * TT + (TT - 1 - tau)) * NN + n];
    g_ds[b * NN + n] = acc;
}

// =====================================================================
// Kernel 2: QKV projections, natural layouts, tf32-rounded outputs.
// =====================================================================
__global__ void qkv_kernel(const float* __restrict__ features,
                           const float* __restrict__ Wq, const float* __restrict__ bq,
                           const float* __restrict__ Wk, const float* __restrict__ bk,
                           const float* __restrict__ Wv, const float* __restrict__ bv,
                           const float* __restrict__ gw)
{
    __shared__ float Ws[3][1024];
    __shared__ float bs[3][32];
    __shared__ float stg[256 * 33];

    int b = blockIdx.y;
    int n0 = blockIdx.x * 256;
    int tid = threadIdx.x;

    for (int i = tid; i < 1024; i += 256) {
        Ws[0][i] = Wq[i]; Ws[1][i] = Wk[i]; Ws[2][i] = Wv[i];
    }
    if (tid < 32) { bs[0][tid] = bq[tid]; bs[1][tid] = bk[tid]; bs[2][tid] = bv[tid]; }
    __syncthreads();

    float geo = 1.f / (1.f + expf(-gw[0]));
    float csq = (1.f - geo) * 0.17677669529663687f * 1.4426950408889634f;

    int n = n0 + tid;
    float4 rf[8];
    const float* fp = features + ((size_t)b * NN + n) * HH;
#pragma unroll
    for (int i = 0; i < 8; i++) rf[i] = *(const float4*)(fp + i * 4);

    float* outp[3] = { g_Q, g_K, g_V };
    for (int pass = 0; pass < 3; pass++) {
#pragma unroll 4
        for (int j = 0; j < 32; j++) {
            float a = bs[pass][j];
#pragma unroll
            for (int i = 0; i < 8; i++) {
                float4 w4 = *(float4*)&Ws[pass][j * 32 + i * 4];
                a += rf[i].x * w4.x + rf[i].y * w4.y + rf[i].z * w4.z + rf[i].w * w4.w;
            }
            if (pass == 0) a *= csq;
            stg[tid * 33 + j] = tf32r(a);
        }
        __syncthreads();
        float* op = outp[pass];
        for (int ch = 0; ch < 32; ch++) {
            int idx = ch * 256 + tid;
            int r = idx >> 5, h = idx & 31;
            op[((size_t)b * NN + n0 + r) * HH + h] = stg[r * 33 + h];
        }
        __syncthreads();
    }
}

// =====================================================================
// Kernel 3: tf32 mma flash attention (no online softmax) + epilogue.
//   CTA: 128 q-rows x 1 batch, 256 threads (8 warps, grid 4m x 2n),
//   key tiles of 64. Warp: 32 q-rows x 32 keys.
// =====================================================================
#define OFF_Q   0          // [128][36]
#define OFF_K   4608       // [64][36]
#define OFF_V   6912       // [64][40]  (row-permuted)
#define OFF_DS  9472       // [2048]
#define OFF_LS  11520      // [2][128]
#define OFF_PR  11776      // [2][128]
#define SMF     12032
#define SMEM_BYTES (SMF * 4)
// epilogue aliases (over Q/K/V/DS region, dead after mainloop)
#define OFF_PART 0         // [128][34]  (even stride -> float2-safe)
#define OFF_CS   4352      // [128][33]
#define OFF_WOS  8576      // [32][33]
#define OFF_BOS  9632
#define OFF_GMS  9664
#define OFF_BTS  9696

__global__ void __launch_bounds__(256, 2) attn_kernel(
    const float* __restrict__ adj, const float* __restrict__ features,
    const float* __restrict__ gw,  const float* __restrict__ Wo,
    const float* __restrict__ bo,  const float* __restrict__ gamma,
    const float* __restrict__ beta, float* __restrict__ out)
{
    extern __shared__ float sm[];
    uint32_t* smu = (uint32_t*)sm;

    const int b    = blockIdx.y;
    const int n0   = blockIdx.x * 128;
    const int tid  = threadIdx.x;
    const int warp = tid >> 5, lane = tid & 31;
    const int wr   = warp >> 1, wc = warp & 1;
    const int g    = lane >> 2, q = lane & 3;
    const int rowbase = wr * 32;

    const float LOG2E = 1.4426950408889634f;
    float geo = 1.f / (1.f + expf(-gw[0]));
    float cg  = geo * 5.f * LOG2E;

    // ---- load Q tile and ds row ----
    for (int i = tid; i < 1024; i += 256) {
        int r = i >> 3, h4 = (i & 7) * 4;
        *(float4*)&sm[OFF_Q + r * 36 + h4] =
            *(const float4*)&g_Q[((size_t)b * NN + n0 + r) * HH + h4];
    }
    for (int i = tid; i < 512; i += 256)
        *(float4*)&sm[OFF_DS + i * 4] = *(const float4*)&g_ds[(size_t)b * NN + i * 4];
    __syncthreads();

    // ---- extract Q fragments (register-resident for all tiles) ----
    uint32_t qa[2][4][4];
#pragma unroll
    for (int mi = 0; mi < 2; mi++)
#pragma unroll
        for (int kk = 0; kk < 4; kk++) {
            int r = rowbase + mi * 16 + g;
            qa[mi][kk][0] = smu[OFF_Q + r       * 36 + kk * 8 + q];
            qa[mi][kk][1] = smu[OFF_Q + (r + 8) * 36 + kk * 8 + q];
            qa[mi][kk][2] = smu[OFF_Q + r       * 36 + kk * 8 + q + 4];
            qa[mi][kk][3] = smu[OFF_Q + (r + 8) * 36 + kk * 8 + q + 4];
        }

    float av[2][4][4];
#pragma unroll
    for (int mi = 0; mi < 2; mi++)
#pragma unroll
        for (int ht = 0; ht < 4; ht++)
#pragma unroll
            for (int e = 0; e < 4; e++) av[mi][ht][e] = 0.f;
    float lr[2][2] = {{0.f,0.f},{0.f,0.f}}, prr[2][2] = {{0.f,0.f},{0.f,0.f}};

    for (int m0 = 0; m0 < NN; m0 += 64) {
        // adj -> S accumulator init (in log2 domain)
        float sd[2][4][4];
#pragma unroll
        for (int mi = 0; mi < 2; mi++)
#pragma unroll
            for (int nt = 0; nt < 4; nt++) {
                size_t r0 = (size_t)(n0 + rowbase + mi * 16 + g) * NN + m0 + wc * 32 + nt * 8 + 2 * q;
                float2 a0 = *(const float2*)&adj[r0];
                float2 a1 = *(const float2*)&adj[r0 + 8 * NN];
                sd[mi][nt][0] = cg * a0.x; sd[mi][nt][1] = cg * a0.y;
                sd[mi][nt][2] = cg * a1.x; sd[mi][nt][3] = cg * a1.y;
            }
        // prefetch K/V tile (64 rows x 32 h each)
        int lc0 = tid >> 3, h4 = (tid & 7) * 4;
        float4 kA = *(const float4*)&g_K[((size_t)b * NN + m0 + lc0)      * HH + h4];
        float4 kB = *(const float4*)&g_K[((size_t)b * NN + m0 + lc0 + 32) * HH + h4];
        float4 vA = *(const float4*)&g_V[((size_t)b * NN + m0 + lc0)      * HH + h4];
        float4 vB = *(const float4*)&g_V[((size_t)b * NN + m0 + lc0 + 32) * HH + h4];

        __syncthreads();   // previous tile's mma reads done
        *(float4*)&sm[OFF_K + lc0 * 36 + h4]        = kA;
        *(float4*)&sm[OFF_K + (lc0 + 32) * 36 + h4] = kB;
        {   // V row permutation: slot = (w&1) ? (w>>1)+4 : (w>>1)
            int w0 = lc0 & 7, base0 = lc0 & ~7;
            int p0 = base0 + ((w0 & 1) ? (w0 >> 1) + 4 : (w0 >> 1));
            *(float4*)&sm[OFF_V + p0 * 40 + h4] = vA;
            int lc1 = lc0 + 32, w1 = lc1 & 7, base1 = lc1 & ~7;
            int p1 = base1 + ((w1 & 1) ? (w1 >> 1) + 4 : (w1 >> 1));
            *(float4*)&sm[OFF_V + p1 * 40 + h4] = vB;
        }
        __syncthreads();

        // ---- S = Q K^T (+adj in C), tf32 mma ----
#pragma unroll
        for (int nt = 0; nt < 4; nt++) {
            int kr = wc * 32 + nt * 8 + g;
#pragma unroll
            for (int kk = 0; kk < 4; kk++) {
                uint32_t b0 = smu[OFF_K + kr * 36 + kk * 8 + q];
                uint32_t b1 = smu[OFF_K + kr * 36 + kk * 8 + q + 4];
                mma_tf32(sd[0][nt], qa[0][kk], b0, b1);
                mma_tf32(sd[1][nt], qa[1][kk], b0, b1);
            }
        }

        // ---- p = exp2(s); accumulate l, pr ----
#pragma unroll
        for (int nt = 0; nt < 4; nt++) {
            float2 dsp = *(const float2*)&sm[OFF_DS + m0 + wc * 32 + nt * 8 + 2 * q];
#pragma unroll
            for (int mi = 0; mi < 2; mi++) {
                float p0 = ex2(sd[mi][nt][0]);
                float p1 = ex2(sd[mi][nt][1]);
                float p2 = ex2(sd[mi][nt][2]);
                float p3 = ex2(sd[mi][nt][3]);
                sd[mi][nt][0] = p0; sd[mi][nt][1] = p1;
                sd[mi][nt][2] = p2; sd[mi][nt][3] = p3;
                lr[mi][0] += p0 + p1;
                lr[mi][1] += p2 + p3;
                prr[mi][0] += p0 * dsp.x + p1 * dsp.y;
                prr[mi][1] += p2 * dsp.x + p3 * dsp.y;
            }
        }

        // ---- attended += P V  (P frags = S D frags reordered; V rows permuted) ----
#pragma unroll
        for (int nt = 0; nt < 4; nt++) {
            uint32_t pa0[4] = { __float_as_uint(sd[0][nt][0]), __float_as_uint(sd[0][nt][2]),
                                __float_as_uint(sd[0][nt][1]), __float_as_uint(sd[0][nt][3]) };
            uint32_t pa1[4] = { __float_as_uint(sd[1][nt][0]), __float_as_uint(sd[1][nt][2]),
                                __float_as_uint(sd[1][nt][1]), __float_as_uint(sd[1][nt][3]) };
            int vr = wc * 32 + nt * 8 + q;
#pragma unroll
            for (int ht = 0; ht < 4; ht++) {
                uint32_t vb0 = smu[OFF_V + vr * 40 + ht * 8 + g];
                uint32_t vb1 = smu[OFF_V + (vr + 4) * 40 + ht * 8 + g];
                mma_tf32(av[0][ht], pa0, vb0, vb1);
                mma_tf32(av[1][ht], pa1, vb0, vb1);
            }
        }
    }

    // ---- epilogue ----
    // quad-reduce l/pr (cols of a row live in a 4-lane group)
#pragma unroll
    for (int mi = 0; mi < 2; mi++)
#pragma unroll
        for (int j = 0; j < 2; j++) {
            float v = lr[mi][j];
            v += __shfl_xor_sync(0xffffffffu, v, 1);
            v += __shfl_xor_sync(0xffffffffu, v, 2);
            lr[mi][j] = v;
            float w = prr[mi][j];
            w += __shfl_xor_sync(0xffffffffu, w, 1);
            w += __shfl_xor_sync(0xffffffffu, w, 2);
            prr[mi][j] = w;
        }

    __syncthreads();   // mainloop smem (Q/K/V/DS) now dead

    if (q == 0) {
#pragma unroll
        for (int mi = 0; mi < 2; mi++) {
            int r = rowbase + mi * 16 + g;
            sm[OFF_LS + wc * 128 + r]     = lr[mi][0];
            sm[OFF_LS + wc * 128 + r + 8] = lr[mi][1];
            sm[OFF_PR + wc * 128 + r]     = prr[mi][0];
            sm[OFF_PR + wc * 128 + r + 8] = prr[mi][1];
        }
    }
    if (wc == 0) {
#pragma unroll
        for (int mi = 0; mi < 2; mi++) {
            int r = rowbase + mi * 16 + g;
#pragma unroll
            for (int ht = 0; ht < 4; ht++) {
                *(float2*)&sm[OFF_PART + r * 34 + ht * 8 + 2 * q] =
                    make_float2(av[mi][ht][0], av[mi][ht][1]);
                *(float2*)&sm[OFF_PART + (r + 8) * 34 + ht * 8 + 2 * q] =
                    make_float2(av[mi][ht][2], av[mi][ht][3]);
            }
        }
    }
    for (int i = tid; i < 1024; i += 256)
        sm[OFF_WOS + (i >> 5) * 33 + (i & 31)] = Wo[i];
    if (tid < 32) {
        sm[OFF_BOS + tid] = bo[tid];
        sm[OFF_GMS + tid] = gamma[tid];
        sm[OFF_BTS + tid] = beta[tid];
    }
    __syncthreads();
    if (wc == 1) {
#pragma unroll
        for (int mi = 0; mi < 2; mi++) {
            int r = rowbase + mi * 16 + g;
#pragma unroll
            for (int ht = 0; ht < 4; ht++) {
                float* p0 = &sm[OFF_PART + r * 34 + ht * 8 + 2 * q];
                p0[0] += av[mi][ht][0]; p0[1] += av[mi][ht][1];
                float* p1 = &sm[OFF_PART + (r + 8) * 34 + ht * 8 + 2 * q];
                p1[0] += av[mi][ht][2]; p1[1] += av[mi][ht][3];
            }
        }
    }
    __syncthreads();

    // combined = features + attended/l + 0.1*pr/l
    {
        int r = tid >> 1, h0 = (tid & 1) * 16;
        float l    = sm[OFF_LS + r] + sm[OFF_LS + 128 + r];
        float invl = 1.f / l;
        float pv   = (sm[OFF_PR + r] + sm[OFF_PR + 128 + r]) * invl * 0.1f;
        const float* fp = &features[((size_t)b * NN + n0 + r) * HH + h0];
#pragma unroll
        for (int h4 = 0; h4 < 16; h4 += 4) {
            float4 f4 = *(const float4*)(fp + h4);
            float fe[4] = { f4.x, f4.y, f4.z, f4.w };
#pragma unroll
            for (int e = 0; e < 4; e++) {
                int h = h0 + h4 + e;
                sm[OFF_CS + r * 33 + h] = fe[e] + sm[OFF_PART + r * 34 + h] * invl + pv;
            }
        }
    }
    __syncthreads();

    // out-proj + LayerNorm (one row per thread)
    if (tid < 128) {
        float cr[32], ho[32];
#pragma unroll
        for (int h = 0; h < 32; h++) cr[h] = sm[OFF_CS + tid * 33 + h];
        float mu = 0.f;
#pragma unroll
        for (int j = 0; j < 32; j++) {
            float a = sm[OFF_BOS + j];
#pragma unroll
            for (int h = 0; h < 32; h++) a += cr[h] * sm[OFF_WOS + j * 33 + h];
            ho[j] = a; mu += a;
        }
        mu *= 0.03125f;
        float var = 0.f;
#pragma unroll
        for (int j = 0; j < 32; j++) { float d = ho[j] - mu; var += d * d; }
        var *= 0.03125f;
        float rs = rsqrtf(var + 1e-5f);
        float* op = out + ((size_t)b * NN + n0 + tid) * HH;
#pragma unroll
        for (int j4 = 0; j4 < 32; j4 += 4) {
            float4 o4;
            o4.x = (ho[j4 + 0] - mu) * rs * sm[OFF_GMS + j4 + 0] + sm[OFF_BTS + j4 + 0];
            o4.y = (ho[j4 + 1] - mu) * rs * sm[OFF_GMS + j4 + 1] + sm[OFF_BTS + j4 + 1];
            o4.z = (ho[j4 + 2] - mu) * rs * sm[OFF_GMS + j4 + 2] + sm[OFF_BTS + j4 + 2];
            o4.w = (ho[j4 + 3] - mu) * rs * sm[OFF_GMS + j4 + 3] + sm[OFF_BTS + j4 + 3];
            *(float4*)(op + j4) = o4;
        }
    }
}

// =====================================================================
extern "C" void kernel_launch(void* const* d_in, const int* in_sizes, int n_in,
                              void* d_out, int out_size)
{
    const float* x        = (const float*)d_in[0];
    const float* features = (const float*)d_in[1];
    const float* dlog     = (const float*)d_in[2];
    const float* Wq       = (const float*)d_in[3];
    const float* bq       = (const float*)d_in[4];
    const float* Wk       = (const float*)d_in[5];
    const float* bk       = (const float*)d_in[6];
    const float* Wv       = (const float*)d_in[7];
    const float* bv       = (const float*)d_in[8];
    const float* adj      = (const float*)d_in[9];
    const float* gw       = (const float*)d_in[10];
    const float* Wo       = (const float*)d_in[11];
    const float* bo       = (const float*)d_in[12];
    const float* gamma    = (const float*)d_in[13];
    const float* beta     = (const float*)d_in[14];
    float* out = (float*)d_out;

    cudaFuncSetAttribute(attn_kernel, cudaFuncAttributeMaxDynamicSharedMemorySize, SMEM_BYTES);

    ds_kernel<<<dim3(NN / 256, BB), 256>>>(x, dlog);
    qkv_kernel<<<dim3(NN / 256, BB), 256>>>(features, Wq, bq, Wk, bk, Wv, bv, gw);
    attn_kernel<<<dim3(NN / 128, BB), 256, SMEM_BYTES>>>(adj, features, gw, Wo, bo, gamma, beta, out);
}